// round 4
// baseline (speedup 1.0000x reference)
#include <cuda_runtime.h>
#include <cuda_bf16.h>

#define N_STEPS   256
#define N_LORS    65536
#define IMG_ELEMS (128*128*128)

// ---------------------------------------------------------------------------
// Kernel 1: zero the accumulator (d_out doubles as the backprojection buffer)
// ---------------------------------------------------------------------------
__global__ void zero_kernel(float4* __restrict__ out) {
    int i = blockIdx.x * blockDim.x + threadIdx.x;
    out[i] = make_float4(0.f, 0.f, 0.f, 0.f);
}

// ---------------------------------------------------------------------------
// voxel index for step st of a LOR; bit-exact with the jax reference:
// separate mul/add (no FMA), IEEE division. Returns -1 if out of bounds.
// ---------------------------------------------------------------------------
__device__ __forceinline__ int step_flat(int st, float p1x, float p1y, float p1z,
                                         float dx, float dy, float dz) {
    const float t  = ((float)st + 0.5f) * (1.0f / N_STEPS);
    const float px = __fadd_rn(p1x, __fmul_rn(t, dx));
    const float py = __fadd_rn(p1y, __fmul_rn(t, dy));
    const float pz = __fadd_rn(p1z, __fmul_rn(t, dz));
    const float fx = floorf(__fdiv_rn(__fadd_rn(px, 150.0f), 2.34375f));
    const float fy = floorf(__fdiv_rn(__fadd_rn(py, 150.0f), 2.34375f));
    const float fz = floorf(__fdiv_rn(__fadd_rn(pz, 150.0f), 2.34375f));
    const bool inb = (fx >= 0.f) && (fx < 128.f) &&
                     (fy >= 0.f) && (fy < 128.f) &&
                     (fz >= 0.f) && (fz < 128.f);
    return inb ? ((((int)fx * 128 + (int)fy) << 7) + (int)fz) : -1;
}

// ---------------------------------------------------------------------------
// Kernel 2: THREAD-per-LOR forward + back projection with full-LOR run dedup.
//   A thread walks all 256 steps; consecutive steps in the same voxel are
//   merged into one load (forward) and one atomic (backward). Runs are no
//   longer split at lane boundaries -> ~14% fewer memory ops than warp-based.
//   Backward pass recomputes indices (bit-identical) instead of storing them.
// ---------------------------------------------------------------------------
__global__ __launch_bounds__(256)
void trace_kernel(const float* __restrict__ img,
                  const float* __restrict__ xl,
                  const float* __restrict__ yl,
                  const float* __restrict__ zl,
                  float* __restrict__ acc) {
    const int tid = blockIdx.x * blockDim.x + threadIdx.x;
    const int set = tid >> 16;            // 0,1,2
    const int lor = tid & (N_LORS - 1);

    const float* lors = (set == 0) ? xl : (set == 1) ? yl : zl;
    const float* L = lors + 7 * lor;

    const float p1x = __ldg(L + 0), p1y = __ldg(L + 1), p1z = __ldg(L + 2);
    const float dx = __fadd_rn(__ldg(L + 3), -p1x);
    const float dy = __fadd_rn(__ldg(L + 4), -p1y);
    const float dz = __fadd_rn(__ldg(L + 5), -p1z);
    const float meas = __ldg(L + 6);
    const float seg = sqrtf(dx*dx + dy*dy + dz*dz) * (1.0f / N_STEPS);

    // ---- forward projection: one load per distinct-voxel run ----
    float s = 0.f;
    float v = 0.f;
    int   prevf = -2;                 // sentinel: != any flat, != -1
    #pragma unroll 2
    for (int c = 0; c < 32; c++) {
        #pragma unroll
        for (int j = 0; j < 8; j++) {
            const int f = step_flat(c * 8 + j, p1x, p1y, p1z, dx, dy, dz);
            if (f != prevf) {
                v = (f >= 0) ? __ldg(img + f) : 0.f;
                prevf = f;
            }
            s += v;
        }
    }

    const float proj = s * seg;
    const float w = meas / (proj + 1e-8f) * seg;   // ratio * seg

    // ---- backprojection: one atomic per distinct-voxel run ----
    int   runflat = -2;
    float runw = 0.f;
    #pragma unroll 2
    for (int c = 0; c < 32; c++) {
        #pragma unroll
        for (int j = 0; j < 8; j++) {
            const int f = step_flat(c * 8 + j, p1x, p1y, p1z, dx, dy, dz);
            if (f == runflat) {
                runw += w;
            } else {
                if (runflat >= 0) atomicAdd(acc + runflat, runw);
                runflat = f;
                runw = w;
            }
        }
    }
    if (runflat >= 0) atomicAdd(acc + runflat, runw);
}

// ---------------------------------------------------------------------------
// Kernel 3: out = image / (eff + eps) * acc   (in-place on d_out)
// ---------------------------------------------------------------------------
__global__ void finalize_kernel(const float4* __restrict__ img,
                                const float4* __restrict__ eff,
                                float4* __restrict__ out) {
    int i = blockIdx.x * blockDim.x + threadIdx.x;
    float4 a = img[i], e = eff[i], o = out[i];
    o.x = a.x / (e.x + 1e-8f) * o.x;
    o.y = a.y / (e.y + 1e-8f) * o.y;
    o.z = a.z / (e.z + 1e-8f) * o.z;
    o.w = a.w / (e.w + 1e-8f) * o.w;
    out[i] = o;
}

extern "C" void kernel_launch(void* const* d_in, const int* in_sizes, int n_in,
                              void* d_out, int out_size) {
    const float* image = (const float*)d_in[0];
    const float* eff   = (const float*)d_in[1];
    const float* xl    = (const float*)d_in[2];
    const float* yl    = (const float*)d_in[3];
    const float* zl    = (const float*)d_in[4];
    float* out = (float*)d_out;

    zero_kernel<<<IMG_ELEMS / 4 / 256, 256>>>((float4*)out);

    const int total_threads = 3 * N_LORS;        // one THREAD per LOR
    trace_kernel<<<total_threads / 256, 256>>>(image, xl, yl, zl, out);

    finalize_kernel<<<IMG_ELEMS / 4 / 256, 256>>>((const float4*)image,
                                                  (const float4*)eff,
                                                  (float4*)out);
}

// round 5
// speedup vs baseline: 1.7674x; 1.7674x over previous
#include <cuda_runtime.h>
#include <cuda_bf16.h>

#define N_STEPS   256
#define N_LORS    65536
#define IMG_ELEMS (128*128*128)

// Image and accumulator in sector-tiled (2x2x2 cube) layout:
// each 32B sector holds one 2x2x2 voxel cube (4.69mm)^3.
__device__ float g_img_cube[IMG_ELEMS];
__device__ float g_acc_cube[IMG_ELEMS];

__device__ __forceinline__ int cube_flat(int ix, int iy, int iz) {
    const int c = (((ix >> 1) << 6) + (iy >> 1)) * 64 + (iz >> 1);
    return (c << 3) + ((ix & 1) << 2) + ((iy & 1) << 1) + (iz & 1);
}

// ---------------------------------------------------------------------------
// Kernel 1: remap image -> cube layout, zero accumulator
// ---------------------------------------------------------------------------
__global__ void remap_kernel(const float* __restrict__ img) {
    const int i = blockIdx.x * blockDim.x + threadIdx.x;   // linear voxel id
    const int ix = i >> 14, iy = (i >> 7) & 127, iz = i & 127;
    g_img_cube[cube_flat(ix, iy, iz)] = img[i];
    g_acc_cube[i] = 0.f;
}

// ---------------------------------------------------------------------------
// Kernel 2: warp-per-LOR. Iteration it covers steps [32*it, 32*it+32) with
// lane = step (consecutive steps across lanes -> warp instruction touches
// only ~4-7 sectors in cube layout; L1TEX coalesces).
//   Forward: flats precomputed, 8 UNCONDITIONAL independent gathers (high MLP,
//            same-address lanes merged by HW).
//   Backward: contiguous same-voxel runs aggregated with shfl/ballot; one
//            atomic per run from the head lane.
// ---------------------------------------------------------------------------
__global__ __launch_bounds__(256)
void trace_kernel(const float* __restrict__ xl,
                  const float* __restrict__ yl,
                  const float* __restrict__ zl) {
    const int warp = blockIdx.x * (blockDim.x >> 5) + (threadIdx.x >> 5);
    const int lane = threadIdx.x & 31;
    const int set  = warp >> 16;          // 0,1,2
    const int lor  = warp & (N_LORS - 1);

    const float* lors = (set == 0) ? xl : (set == 1) ? yl : zl;
    const float* L = lors + 7 * lor;

    const float p1x = L[0], p1y = L[1], p1z = L[2];
    const float dx = __fadd_rn(L[3], -p1x);
    const float dy = __fadd_rn(L[4], -p1y);
    const float dz = __fadd_rn(L[5], -p1z);
    const float meas = L[6];
    const float seg = sqrtf(dx*dx + dy*dy + dz*dz) * (1.0f / N_STEPS);

    int flats[8];

    // ---- index computation (bit-exact with jax: no FMA, IEEE div) ----
    #pragma unroll
    for (int it = 0; it < 8; it++) {
        const int   st = it * 32 + lane;
        const float t  = ((float)st + 0.5f) * (1.0f / N_STEPS);
        const float px = __fadd_rn(p1x, __fmul_rn(t, dx));
        const float py = __fadd_rn(p1y, __fmul_rn(t, dy));
        const float pz = __fadd_rn(p1z, __fmul_rn(t, dz));
        const float fx = floorf(__fdiv_rn(__fadd_rn(px, 150.0f), 2.34375f));
        const float fy = floorf(__fdiv_rn(__fadd_rn(py, 150.0f), 2.34375f));
        const float fz = floorf(__fdiv_rn(__fadd_rn(pz, 150.0f), 2.34375f));
        const bool inb = (fx >= 0.f) && (fx < 128.f) &&
                         (fy >= 0.f) && (fy < 128.f) &&
                         (fz >= 0.f) && (fz < 128.f);
        flats[it] = inb ? cube_flat((int)fx, (int)fy, (int)fz) : -1;
    }

    // ---- forward projection: 8 independent (mostly coalesced) gathers ----
    float s = 0.f;
    #pragma unroll
    for (int it = 0; it < 8; it++) {
        const int f = flats[it];
        s += (f >= 0) ? __ldg(g_img_cube + f) : 0.f;
    }

    #pragma unroll
    for (int o = 16; o > 0; o >>= 1)
        s += __shfl_xor_sync(0xffffffffu, s, o);

    const float proj = s * seg;
    const float w = meas / (proj + 1e-8f) * seg;   // ratio * seg

    // ---- backprojection: one atomic per contiguous same-voxel run ----
    #pragma unroll
    for (int it = 0; it < 8; it++) {
        const int f = flats[it];
        const int fprev = __shfl_up_sync(0xffffffffu, f, 1);
        const bool head = (lane == 0) || (f != fprev);
        const unsigned b = __ballot_sync(0xffffffffu, head);
        if (head && f >= 0) {
            const unsigned rest = (b >> lane) >> 1;   // heads after me
            const int cnt = rest ? __ffs(rest) : (32 - lane);
            atomicAdd(g_acc_cube + f, w * (float)cnt);
        }
    }
}

// ---------------------------------------------------------------------------
// Kernel 3: out = image / (eff + eps) * acc   (gather from cube layout)
// ---------------------------------------------------------------------------
__global__ void finalize_kernel(const float* __restrict__ img,
                                const float* __restrict__ eff,
                                float* __restrict__ out) {
    const int i = blockIdx.x * blockDim.x + threadIdx.x;
    const int ix = i >> 14, iy = (i >> 7) & 127, iz = i & 127;
    const float a = g_acc_cube[cube_flat(ix, iy, iz)];
    out[i] = img[i] / (eff[i] + 1e-8f) * a;
}

extern "C" void kernel_launch(void* const* d_in, const int* in_sizes, int n_in,
                              void* d_out, int out_size) {
    const float* image = (const float*)d_in[0];
    const float* eff   = (const float*)d_in[1];
    const float* xl    = (const float*)d_in[2];
    const float* yl    = (const float*)d_in[3];
    const float* zl    = (const float*)d_in[4];
    float* out = (float*)d_out;

    remap_kernel<<<IMG_ELEMS / 256, 256>>>(image);

    const int total_warps = 3 * N_LORS;          // one warp per LOR
    trace_kernel<<<total_warps / 8, 256>>>(xl, yl, zl);

    finalize_kernel<<<IMG_ELEMS / 256, 256>>>(image, eff, out);
}

// round 6
// speedup vs baseline: 2.3756x; 1.3441x over previous
#include <cuda_runtime.h>
#include <cuda_bf16.h>

#define N_STEPS   256
#define N_LORS    65536
#define IMG_ELEMS (128*128*128)

// ---------------------------------------------------------------------------
// Kernel 1: zero the accumulator (d_out doubles as the backprojection buffer)
// ---------------------------------------------------------------------------
__global__ void zero_kernel(float4* __restrict__ out) {
    int i = blockIdx.x * blockDim.x + threadIdx.x;
    out[i] = make_float4(0.f, 0.f, 0.f, 0.f);
}

// Correctly-rounded reciprocal of 2.34375 (compile-time, round-to-nearest).
#define RCP_VOX (1.0f / 2.34375f)
#define VOX     2.34375f

// div.rn(x, VOX) via correctly-rounded reciprocal + 2 Markstein FMA steps.
// Matches IEEE division (what the jax reference lowers to) bit-for-bit for
// these benign operand ranges, at ~half the instruction count and no branches.
__device__ __forceinline__ float div_vox(float x) {
    float q = __fmul_rn(x, RCP_VOX);
    q = __fmaf_rn(__fmaf_rn(-VOX, q, x), RCP_VOX, q);
    q = __fmaf_rn(__fmaf_rn(-VOX, q, x), RCP_VOX, q);
    return q;
}

// ---------------------------------------------------------------------------
// Kernel 2: warp-per-LOR. Iteration it covers steps [32*it, 32*it+32) with
// lane = step. Index math is bit-exact with the jax reference (separate
// mul/add, correctly-rounded division) but instruction-minimized: the kernel
// is fp-pipe bound, not memory bound.
// ---------------------------------------------------------------------------
__global__ __launch_bounds__(256)
void trace_kernel(const float* __restrict__ img,
                  const float* __restrict__ xl,
                  const float* __restrict__ yl,
                  const float* __restrict__ zl,
                  float* __restrict__ acc) {
    const int warp = blockIdx.x * (blockDim.x >> 5) + (threadIdx.x >> 5);
    const int lane = threadIdx.x & 31;
    const int set  = warp >> 16;          // 0,1,2
    const int lor  = warp & (N_LORS - 1);

    const float* lors = (set == 0) ? xl : (set == 1) ? yl : zl;
    const float* L = lors + 7 * lor;

    const float p1x = L[0], p1y = L[1], p1z = L[2];
    const float dx = __fadd_rn(L[3], -p1x);
    const float dy = __fadd_rn(L[4], -p1y);
    const float dz = __fadd_rn(L[5], -p1z);
    const float meas = L[6];
    const float seg = sqrtf(dx*dx + dy*dy + dz*dz) * (1.0f / N_STEPS);

    int flats[8];

    // t for lane's step in iteration 0; incrementing by 0.125f per iteration
    // is EXACT (all t are multiples of 2^-9), so it matches (st+0.5)/256.
    float t = ((float)lane + 0.5f) * (1.0f / N_STEPS);

    #pragma unroll
    for (int it = 0; it < 8; it++) {
        // pos = p1 + t*d, separate mul/add (no contraction) to match jax
        const float px = __fadd_rn(p1x, __fmul_rn(t, dx));
        const float py = __fadd_rn(p1y, __fmul_rn(t, dy));
        const float pz = __fadd_rn(p1z, __fmul_rn(t, dz));
        // floor((pos+150)/2.34375) -> int, directly as float2int_rd
        const int ix = __float2int_rd(div_vox(__fadd_rn(px, 150.0f)));
        const int iy = __float2int_rd(div_vox(__fadd_rn(py, 150.0f)));
        const int iz = __float2int_rd(div_vox(__fadd_rn(pz, 150.0f)));
        const bool inb = ((unsigned)ix < 128u) & ((unsigned)iy < 128u) &
                         ((unsigned)iz < 128u);
        flats[it] = inb ? (((ix << 7) + iy) << 7) + iz : -1;
        t = __fadd_rn(t, 0.125f);
    }

    // ---- forward projection: 8 independent gathers ----
    float s = 0.f;
    #pragma unroll
    for (int it = 0; it < 8; it++) {
        const int f = flats[it];
        s += (f >= 0) ? __ldg(img + f) : 0.f;
    }

    #pragma unroll
    for (int o = 16; o > 0; o >>= 1)
        s += __shfl_xor_sync(0xffffffffu, s, o);

    const float proj = s * seg;
    const float w = meas / (proj + 1e-8f) * seg;   // ratio * seg

    // ---- backprojection: one atomic per contiguous same-voxel run ----
    #pragma unroll
    for (int it = 0; it < 8; it++) {
        const int f = flats[it];
        const int fprev = __shfl_up_sync(0xffffffffu, f, 1);
        const bool head = (lane == 0) || (f != fprev);
        const unsigned b = __ballot_sync(0xffffffffu, head);
        if (head && f >= 0) {
            const unsigned rest = (b >> lane) >> 1;   // heads after me
            const int cnt = rest ? __ffs(rest) : (32 - lane);
            atomicAdd(acc + f, w * (float)cnt);
        }
    }
}

// ---------------------------------------------------------------------------
// Kernel 3: out = image / (eff + eps) * acc   (in-place on d_out)
// ---------------------------------------------------------------------------
__global__ void finalize_kernel(const float4* __restrict__ img,
                                const float4* __restrict__ eff,
                                float4* __restrict__ out) {
    int i = blockIdx.x * blockDim.x + threadIdx.x;
    float4 a = img[i], e = eff[i], o = out[i];
    o.x = a.x / (e.x + 1e-8f) * o.x;
    o.y = a.y / (e.y + 1e-8f) * o.y;
    o.z = a.z / (e.z + 1e-8f) * o.z;
    o.w = a.w / (e.w + 1e-8f) * o.w;
    out[i] = o;
}

extern "C" void kernel_launch(void* const* d_in, const int* in_sizes, int n_in,
                              void* d_out, int out_size) {
    const float* image = (const float*)d_in[0];
    const float* eff   = (const float*)d_in[1];
    const float* xl    = (const float*)d_in[2];
    const float* yl    = (const float*)d_in[3];
    const float* zl    = (const float*)d_in[4];
    float* out = (float*)d_out;

    zero_kernel<<<IMG_ELEMS / 4 / 256, 256>>>((float4*)out);

    const int total_warps = 3 * N_LORS;          // one warp per LOR
    trace_kernel<<<total_warps / 8, 256>>>(image, xl, yl, zl, out);

    finalize_kernel<<<IMG_ELEMS / 4 / 256, 256>>>((const float4*)image,
                                                  (const float4*)eff,
                                                  (float4*)out);
}